// round 7
// baseline (speedup 1.0000x reference)
#include <cuda_runtime.h>

// HMLoss: 4-region histogram-matching L1 loss, H=W=2048.
// R7: persistent kernel + dynamic work-stealing. R6 showed ~17us of the 71.6us
// is blocks spinning at the global barriers behind the slowest statically-
// partitioned block. Chunked dynamic assignment (512 quads/grab, ~7 grabs per
// block) flattens both phase tails. Hist/loss/table bodies unchanged.

#define NQ    1048576   // (2048*2048)/4
#define NB    256
#define NHIST 24
#define GRID  296
#define TPB   512
#define CHUNK 512       // quads per grab == TPB -> 1 quad/thread/grab
#define NCHUNK (NQ / CHUNK)   // 2048

__device__ unsigned int g_hist[NHIST * NB];   // zero at load; self-cleaning
__device__ float        g_tables[12 * NB];
__device__ double       g_acc;
__device__ unsigned int g_bar1, g_bar2, g_ticket;
__device__ unsigned int g_work1, g_work2;

// Packed label LUTs (labels 0..18).
// A (mask_A): low16 = src hist base + 1 (0 = unmasked), bit16 = (label==11)
// B (mask_B): low16 = tar hist base + 1 for hair/eye (0 = none), bit16 = in tar face set
__constant__ int c_lutA[32] = {
    0, 1, 3073, 4609, 3073, 4609, 0,
    1, 1, 0, 1, 1 | (1 << 16), 0, 0,
    1, 0, 0, 1537, 0,
    0,0,0,0,0,0,0,0,0,0,0,0,0
};
__constant__ int c_lutB[32] = {
    0, (1<<16), 3841, 5377, 3841, 5377, 0,
    (1<<16), (1<<16), 0, (1<<16), 0, 0, 0,
    (1<<16), 0, 0, 2305, 0,
    0,0,0,0,0,0,0,0,0,0,0,0,0
};

__device__ __forceinline__ int floor_pos(float x) {
    return __float_as_int(__fadd_rz(x, 8388608.0f)) & 0x7FFFFF;
}
__device__ __forceinline__ float sat01(float x) {
    return __saturatef(fmaf(x, 0.5f, 0.5f));
}

__device__ __forceinline__ void hist_px(int la, int lb,
                                        float fa, float fb, float fc,
                                        float ra, float rb, float rc,
                                        const int* lutA, const int* lutB,
                                        unsigned int* sh)
{
    int da = lutA[la];
    int db = lutB[lb];

    int sbase = (da & 0xFFFF) - 1;
    if (sbase >= 0) {
        int b0 = min(floor_pos(sat01(fa) * 256.0f), 255);
        int b1 = min(floor_pos(sat01(fb) * 256.0f), 255);
        int b2 = min(floor_pos(sat01(fc) * 256.0f), 255);
        atomicAdd(&sh[sbase          + b0], 1u);
        atomicAdd(&sh[sbase +     NB + b1], 1u);
        atomicAdd(&sh[sbase + 2 * NB + b2], 1u);
    }

    int faceval = ((da >> 16) & 1) + ((db >> 16) & 1);
    int tbase = (db & 0xFFFF) - 1;
    if ((faceval | (tbase + 1)) != 0) {
        float scale = (faceval == 2) ? 512.0f : 256.0f;   // faceval==2 implies tbase<0
        int b0 = min(floor_pos(sat01(ra) * scale), 255);
        int b1 = min(floor_pos(sat01(rb) * scale), 255);
        int b2 = min(floor_pos(sat01(rc) * scale), 255);
        if (faceval > 0) {
            atomicAdd(&sh[3 * NB          + b0], 1u);
            atomicAdd(&sh[3 * NB +     NB + b1], 1u);
            atomicAdd(&sh[3 * NB + 2 * NB + b2], 1u);
        }
        if (tbase >= 0) {
            atomicAdd(&sh[tbase          + b0], 1u);
            atomicAdd(&sh[tbase +     NB + b1], 1u);
            atomicAdd(&sh[tbase + 2 * NB + b2], 1u);
        }
    }
}

__device__ __forceinline__ float loss_px(int la, float fa, float fb, float fc,
                                         const int* lutA, const float* tbl)
{
    int sbase = ((lutA[la] & 0xFFFF) - 1) >> 1;   // src hist base/2 == region*3*NB
    float s = 0.0f;
    if (sbase >= 0) {
        const float* tb = tbl + sbase;
        float v0 = sat01(fa) * 255.0f;
        float v1 = sat01(fb) * 255.0f;
        float v2 = sat01(fc) * 255.0f;
        int i0 = min(floor_pos(v0), 255);
        int i1 = min(floor_pos(v1), 255);
        int i2 = min(floor_pos(v2), 255);
        s = fabsf(v0 - tb[i0]) + fabsf(v1 - tb[NB + i1]) + fabsf(v2 - tb[2 * NB + i2]);
    }
    return s;
}

__global__ void __launch_bounds__(TPB, 2) fused_kernel(
    const float4* __restrict__ fake, const float4* __restrict__ refb,
    const int4* __restrict__ ma, const int4* __restrict__ mb, float* out)
{
    __shared__ unsigned int sh[NHIST * NB];   // phase1 hists / phase2 scratch / phase3 tables
    __shared__ int lutA[32], lutB[32];
    __shared__ float wsum[16];
    __shared__ unsigned int s_chunk;

    const int tid = threadIdx.x;
    const int bid = blockIdx.x;

    for (int i = tid; i < NHIST * NB; i += TPB) sh[i] = 0u;
    if (tid < 32) { lutA[tid] = c_lutA[tid]; lutB[tid] = c_lutB[tid]; }
    __syncthreads();

    // ---------------- phase 1: histograms (work-stealing) ----------------
    for (;;) {
        if (tid == 0) s_chunk = atomicAdd(&g_work1, 1u);
        __syncthreads();
        unsigned c = s_chunk;
        __syncthreads();
        if (c >= NCHUNK) break;
        int q = (int)c * CHUNK + tid;
        {
            int4   a4 = ma[q],  b4 = mb[q];
            float4 f0 = fake[q], f1 = fake[q + NQ], f2 = fake[q + 2 * NQ];
            float4 r0 = refb[q], r1 = refb[q + NQ], r2 = refb[q + 2 * NQ];
            hist_px(a4.x, b4.x, f0.x, f1.x, f2.x, r0.x, r1.x, r2.x, lutA, lutB, sh);
            hist_px(a4.y, b4.y, f0.y, f1.y, f2.y, r0.y, r1.y, r2.y, lutA, lutB, sh);
            hist_px(a4.z, b4.z, f0.z, f1.z, f2.z, r0.z, r1.z, r2.z, lutA, lutB, sh);
            hist_px(a4.w, b4.w, f0.w, f1.w, f2.w, r0.w, r1.w, r2.w, lutA, lutB, sh);
        }
    }
    __syncthreads();
    for (int i = tid; i < NHIST * NB; i += TPB) {
        unsigned v = sh[i];
        if (v) atomicAdd(&g_hist[i], v);
    }

    // ---------------- barrier 1 (one wave: all 296 blocks resident) ----------------
    __syncthreads();
    if (tid == 0) {
        __threadfence();
        atomicAdd(&g_bar1, 1u);
        while (*(volatile unsigned int*)&g_bar1 < GRID) { }
        __threadfence();
    }
    __syncthreads();

    // ---------------- phase 2: tables (blocks 0..11) + g_hist self-clean ----------------
    if (bid < 12) {
        unsigned* cs = sh;                 // [256] src counts
        unsigned* ct = sh + NB;            // [256] tar counts
        float* cd = (float*)(sh + 2 * NB);
        float* ca = (float*)(sh + 3 * NB);
        int region = bid / 3, c = bid % 3;
        int isrc = (region * 6 + c) * NB;
        int itar = (region * 6 + 3 + c) * NB;

        if (tid < NB) {
            cs[tid] = g_hist[isrc + tid];
            ct[tid] = g_hist[itar + tid];
            g_hist[isrc + tid] = 0u;
            g_hist[itar + tid] = 0u;
        }
        __syncthreads();
        if (tid < 2) {
            const unsigned* h = (tid == 0) ? cs : ct;
            float tot = 0.0f;
            for (int k = 0; k < NB; k++) tot += (float)h[k];   // exact (< 2^24)
            tot = fmaxf(tot, 1.0f);
            float run = 0.0f;
            float* dst = (tid == 0) ? cd : ca;
            for (int k = 0; k < NB; k++) { run += (float)h[k] / tot; dst[k] = run; }
        }
        __syncthreads();
        if (tid < NB) {
            float dc = cd[tid];
            int tbl = tid;
            for (int k = 0; k < 255; k++) {
                if (dc >= ca[k] && dc <= ca[k + 1]) { tbl = k + 1; break; }
            }
            if (tid == 0)   tbl = 0;
            if (tid == 255) tbl = 255;
            g_tables[bid * NB + tid] = (float)tbl;
        }
        __syncthreads();
        if (tid == 0) {
            __threadfence();
            atomicAdd(&g_bar2, 1u);
        }
    }

    // ---------------- barrier 2: all 12 tables ready ----------------
    if (tid == 0) {
        while (*(volatile unsigned int*)&g_bar2 < 12u) { }
        __threadfence();
    }
    __syncthreads();

    // ---------------- phase 3: L1 loss (work-stealing) ----------------
    float* tbl = (float*)sh;
    for (int i = tid; i < 12 * NB; i += TPB) tbl[i] = g_tables[i];
    __syncthreads();

    float acc = 0.0f;
    for (;;) {
        if (tid == 0) s_chunk = atomicAdd(&g_work2, 1u);
        __syncthreads();
        unsigned c = s_chunk;
        __syncthreads();
        if (c >= NCHUNK) break;
        int q = (int)c * CHUNK + tid;
        {
            int4   a4 = ma[q];
            float4 f0 = fake[q], f1 = fake[q + NQ], f2 = fake[q + 2 * NQ];
            acc += loss_px(a4.x, f0.x, f1.x, f2.x, lutA, tbl);
            acc += loss_px(a4.y, f0.y, f1.y, f2.y, lutA, tbl);
            acc += loss_px(a4.z, f0.z, f1.z, f2.z, lutA, tbl);
            acc += loss_px(a4.w, f0.w, f1.w, f2.w, lutA, tbl);
        }
    }

    #pragma unroll
    for (int off = 16; off > 0; off >>= 1)
        acc += __shfl_down_sync(0xffffffffu, acc, off);
    int lane = tid & 31, wid = tid >> 5;
    if (lane == 0) wsum[wid] = acc;
    __syncthreads();
    if (tid == 0) {
        float s = 0.0f;
        #pragma unroll
        for (int i = 0; i < 16; i++) s += wsum[i];
        atomicAdd(&g_acc, (double)s);
        __threadfence();
        unsigned t = atomicAdd(&g_ticket, 1u);
        if (t == GRID - 1) {
            double total = *((volatile double*)&g_acc);
            out[0] = (float)(total * (0.1 / 12582912.0));  // 0.1/(3*H*W)
            // reset all state for next graph replay
            g_acc = 0.0;
            g_bar1 = 0u;
            g_bar2 = 0u;
            g_ticket = 0u;
            g_work1 = 0u;
            g_work2 = 0u;
        }
    }
}

extern "C" void kernel_launch(void* const* d_in, const int* in_sizes, int n_in,
                              void* d_out, int out_size)
{
    (void)in_sizes; (void)n_in; (void)out_size;
    const float4* fake = (const float4*)d_in[0];
    const float4* refb = (const float4*)d_in[1];
    const int4*   ma   = (const int4*)d_in[2];
    const int4*   mb   = (const int4*)d_in[3];
    float* out = (float*)d_out;

    fused_kernel<<<GRID, TPB>>>(fake, refb, ma, mb, out);
}

// round 8
// speedup vs baseline: 1.1176x; 1.1176x over previous
#include <cuda_runtime.h>

// HMLoss: 4-region histogram-matching L1 loss, H=W=2048.
// R8: two launches total (each sync point costs ~4-5us on this setup:
// R2 profiled a 1-thread kernel at 4.6us).
//   K1 hist (proven R5 body, 296x512).
//   K2 table+loss: blocks 0-11 compute the 12 tables (and zero g_hist for the
//      next replay), all 592 blocks spin on a 12-arrival flag, then run the
//      proven loss body; last-ticket block finalizes and resets state.

#define NQ    1048576   // (2048*2048)/4
#define NB    256
#define NHIST 24

__device__ unsigned int g_hist[NHIST * NB];   // zeroed at load; self-cleaning
__device__ float        g_tables[12 * NB];
__device__ double       g_acc;
__device__ unsigned int g_tbar, g_ticket;

#define LOSS_GRID 592

// Packed label LUTs (labels 0..18).
// A (mask_A): low16 = src hist base + 1 (0 = unmasked), bit16 = (label==11)
// B (mask_B): low16 = tar hist base + 1 for hair/eye (0 = none), bit16 = in tar face set
__constant__ int c_lutA[32] = {
    0, 1, 3073, 4609, 3073, 4609, 0,
    1, 1, 0, 1, 1 | (1 << 16), 0, 0,
    1, 0, 0, 1537, 0,
    0,0,0,0,0,0,0,0,0,0,0,0,0
};
__constant__ int c_lutB[32] = {
    0, (1<<16), 3841, 5377, 3841, 5377, 0,
    (1<<16), (1<<16), 0, (1<<16), 0, 0, 0,
    (1<<16), 0, 0, 2305, 0,
    0,0,0,0,0,0,0,0,0,0,0,0,0
};

// floor for x in [0, 2^23): round-toward-zero add of 2^23, take mantissa bits.
__device__ __forceinline__ int floor_pos(float x) {
    return __float_as_int(__fadd_rz(x, 8388608.0f)) & 0x7FFFFF;
}
// saturate((x+1)/2)
__device__ __forceinline__ float sat01(float x) {
    return __saturatef(fmaf(x, 0.5f, 0.5f));
}

// ---------------------------------------------------------------- K1: histograms
__device__ __forceinline__ void hist_px(int la, int lb,
                                        float fa, float fb, float fc,
                                        float ra, float rb, float rc,
                                        const int* lutA, const int* lutB,
                                        unsigned int* sh)
{
    int da = lutA[la];
    int db = lutB[lb];

    int sbase = (da & 0xFFFF) - 1;
    if (sbase >= 0) {
        int b0 = min(floor_pos(sat01(fa) * 256.0f), 255);
        int b1 = min(floor_pos(sat01(fb) * 256.0f), 255);
        int b2 = min(floor_pos(sat01(fc) * 256.0f), 255);
        atomicAdd(&sh[sbase          + b0], 1u);
        atomicAdd(&sh[sbase +     NB + b1], 1u);
        atomicAdd(&sh[sbase + 2 * NB + b2], 1u);
    }

    int faceval = ((da >> 16) & 1) + ((db >> 16) & 1);
    int tbase = (db & 0xFFFF) - 1;
    if ((faceval | (tbase + 1)) != 0) {
        float scale = (faceval == 2) ? 512.0f : 256.0f;   // faceval==2 implies tbase<0
        int b0 = min(floor_pos(sat01(ra) * scale), 255);
        int b1 = min(floor_pos(sat01(rb) * scale), 255);
        int b2 = min(floor_pos(sat01(rc) * scale), 255);
        if (faceval > 0) {
            atomicAdd(&sh[3 * NB          + b0], 1u);
            atomicAdd(&sh[3 * NB +     NB + b1], 1u);
            atomicAdd(&sh[3 * NB + 2 * NB + b2], 1u);
        }
        if (tbase >= 0) {
            atomicAdd(&sh[tbase          + b0], 1u);
            atomicAdd(&sh[tbase +     NB + b1], 1u);
            atomicAdd(&sh[tbase + 2 * NB + b2], 1u);
        }
    }
}

__global__ void __launch_bounds__(512, 2) hist_kernel(
    const float4* __restrict__ fake, const float4* __restrict__ refb,
    const int4* __restrict__ ma, const int4* __restrict__ mb)
{
    __shared__ unsigned int sh[NHIST * NB];
    __shared__ int lutA[32], lutB[32];
    for (int i = threadIdx.x; i < NHIST * NB; i += 512) sh[i] = 0u;
    if (threadIdx.x < 32) { lutA[threadIdx.x] = c_lutA[threadIdx.x];
                            lutB[threadIdx.x] = c_lutB[threadIdx.x]; }
    __syncthreads();

    int stride = gridDim.x * 512;
    for (int q = blockIdx.x * 512 + threadIdx.x; q < NQ; q += stride) {
        int4   a4 = ma[q],  b4 = mb[q];
        float4 f0 = fake[q], f1 = fake[q + NQ], f2 = fake[q + 2 * NQ];
        float4 r0 = refb[q], r1 = refb[q + NQ], r2 = refb[q + 2 * NQ];
        hist_px(a4.x, b4.x, f0.x, f1.x, f2.x, r0.x, r1.x, r2.x, lutA, lutB, sh);
        hist_px(a4.y, b4.y, f0.y, f1.y, f2.y, r0.y, r1.y, r2.y, lutA, lutB, sh);
        hist_px(a4.z, b4.z, f0.z, f1.z, f2.z, r0.z, r1.z, r2.z, lutA, lutB, sh);
        hist_px(a4.w, b4.w, f0.w, f1.w, f2.w, r0.w, r1.w, r2.w, lutA, lutB, sh);
    }
    __syncthreads();
    for (int i = threadIdx.x; i < NHIST * NB; i += 512) {
        unsigned v = sh[i];
        if (v) atomicAdd(&g_hist[i], v);
    }
}

// ---------------------------------------------------------------- K2: tables + loss
__device__ __forceinline__ float loss_px(int la, float fa, float fb, float fc,
                                         const int* lutA, const float* tbl)
{
    int sbase = ((lutA[la] & 0xFFFF) - 1) >> 1;   // src hist base/2 == region*3*NB
    float s = 0.0f;
    if (sbase >= 0) {
        const float* tb = tbl + sbase;
        float v0 = sat01(fa) * 255.0f;
        float v1 = sat01(fb) * 255.0f;
        float v2 = sat01(fc) * 255.0f;
        int i0 = min(floor_pos(v0), 255);
        int i1 = min(floor_pos(v1), 255);
        int i2 = min(floor_pos(v2), 255);
        s = fabsf(v0 - tb[i0]) + fabsf(v1 - tb[NB + i1]) + fabsf(v2 - tb[2 * NB + i2]);
    }
    return s;
}

__global__ void __launch_bounds__(256) table_loss_kernel(
    const float4* __restrict__ fake, const int4* __restrict__ ma, float* out)
{
    __shared__ float tbl[12 * NB];      // loss-phase table cache (reused as scratch)
    __shared__ int lutA[32];
    __shared__ float wsum[8];

    const int tid = threadIdx.x;
    const int bid = blockIdx.x;

    if (tid < 32) lutA[tid] = c_lutA[tid];

    // ---- prologue: blocks 0..11 build one table each (+ self-clean g_hist)
    if (bid < 12) {
        unsigned* cs = (unsigned*)tbl;          // [256]
        unsigned* ct = (unsigned*)tbl + NB;     // [256]
        float* cd = tbl + 2 * NB;               // [256]
        float* ca = tbl + 3 * NB;               // [256]
        int region = bid / 3, c = bid % 3;
        int isrc = (region * 6 + c) * NB;
        int itar = (region * 6 + 3 + c) * NB;

        cs[tid] = g_hist[isrc + tid];
        ct[tid] = g_hist[itar + tid];
        g_hist[isrc + tid] = 0u;                // restore zeros for next replay
        g_hist[itar + tid] = 0u;
        __syncthreads();
        if (tid < 2) {
            const unsigned* h = (tid == 0) ? cs : ct;
            float tot = 0.0f;
            for (int k = 0; k < NB; k++) tot += (float)h[k];   // exact (< 2^24)
            tot = fmaxf(tot, 1.0f);
            float run = 0.0f;
            float* dst = (tid == 0) ? cd : ca;
            for (int k = 0; k < NB; k++) { run += (float)h[k] / tot; dst[k] = run; }
        }
        __syncthreads();
        {
            float dc = cd[tid];
            int t = tid;
            for (int k = 0; k < 255; k++) {
                if (dc >= ca[k] && dc <= ca[k + 1]) { t = k + 1; break; }
            }
            if (tid == 0)   t = 0;
            if (tid == 255) t = 255;
            g_tables[bid * NB + tid] = (float)t;
        }
        __syncthreads();
        if (tid == 0) {
            __threadfence();
            atomicAdd(&g_tbar, 1u);
        }
    }

    // ---- wait until all 12 tables are published (grid is one wave: 4 blk/SM)
    if (tid == 0) {
        while (*(volatile unsigned int*)&g_tbar < 12u) { }
        __threadfence();
    }
    __syncthreads();

    // ---- loss phase (proven R1 body)
    for (int i = tid; i < 12 * NB; i += 256) tbl[i] = g_tables[i];
    __syncthreads();

    float acc = 0.0f;
    int stride = gridDim.x * 256;
    for (int q = bid * 256 + tid; q < NQ; q += stride) {
        int4   a4 = ma[q];
        float4 f0 = fake[q], f1 = fake[q + NQ], f2 = fake[q + 2 * NQ];
        acc += loss_px(a4.x, f0.x, f1.x, f2.x, lutA, tbl);
        acc += loss_px(a4.y, f0.y, f1.y, f2.y, lutA, tbl);
        acc += loss_px(a4.z, f0.z, f1.z, f2.z, lutA, tbl);
        acc += loss_px(a4.w, f0.w, f1.w, f2.w, lutA, tbl);
    }

    #pragma unroll
    for (int off = 16; off > 0; off >>= 1)
        acc += __shfl_down_sync(0xffffffffu, acc, off);
    int lane = tid & 31, wid = tid >> 5;
    if (lane == 0) wsum[wid] = acc;
    __syncthreads();
    if (tid == 0) {
        float s = 0.0f;
        #pragma unroll
        for (int i = 0; i < 8; i++) s += wsum[i];
        atomicAdd(&g_acc, (double)s);
        __threadfence();
        unsigned t = atomicAdd(&g_ticket, 1u);
        if (t == (unsigned)(gridDim.x - 1)) {
            double total = *((volatile double*)&g_acc);
            out[0] = (float)(total * (0.1 / 12582912.0));  // 0.1/(3*H*W)
            g_acc = 0.0;
            g_tbar = 0u;
            g_ticket = 0u;
        }
    }
}

// ---------------------------------------------------------------- launch
extern "C" void kernel_launch(void* const* d_in, const int* in_sizes, int n_in,
                              void* d_out, int out_size)
{
    (void)in_sizes; (void)n_in; (void)out_size;
    const float4* fake = (const float4*)d_in[0];
    const float4* refb = (const float4*)d_in[1];
    const int4*   ma   = (const int4*)d_in[2];
    const int4*   mb   = (const int4*)d_in[3];
    float* out = (float*)d_out;

    hist_kernel      <<<296, 512>>>(fake, refb, ma, mb);
    table_loss_kernel<<<LOSS_GRID, 256>>>(fake, ma, out);
}

// round 9
// speedup vs baseline: 1.3564x; 1.2136x over previous
#include <cuda_runtime.h>

// HMLoss: 4-region histogram-matching L1 loss, H=W=2048.
// R9: R8 structure (2 launches), with the K2 prologue parallelized:
//   - exact f32 tree-reduction for totals (integer counts < 2^24 -> order-free)
//   - per-bin division elementwise (identical rounding to reference)
//   - Hillis-Steele 8-step scan replaces the 256-long sequential cumsum chain
//   - __nanosleep backoff in the table-ready spin (kills same-address L2 flood)

#define NQ    1048576   // (2048*2048)/4
#define NB    256
#define NHIST 24

__device__ unsigned int g_hist[NHIST * NB];   // zeroed at load; self-cleaning
__device__ float        g_tables[12 * NB];
__device__ double       g_acc;
__device__ unsigned int g_tbar, g_ticket;

#define LOSS_GRID 592

// Packed label LUTs (labels 0..18).
// A (mask_A): low16 = src hist base + 1 (0 = unmasked), bit16 = (label==11)
// B (mask_B): low16 = tar hist base + 1 for hair/eye (0 = none), bit16 = in tar face set
__constant__ int c_lutA[32] = {
    0, 1, 3073, 4609, 3073, 4609, 0,
    1, 1, 0, 1, 1 | (1 << 16), 0, 0,
    1, 0, 0, 1537, 0,
    0,0,0,0,0,0,0,0,0,0,0,0,0
};
__constant__ int c_lutB[32] = {
    0, (1<<16), 3841, 5377, 3841, 5377, 0,
    (1<<16), (1<<16), 0, (1<<16), 0, 0, 0,
    (1<<16), 0, 0, 2305, 0,
    0,0,0,0,0,0,0,0,0,0,0,0,0
};

// floor for x in [0, 2^23): round-toward-zero add of 2^23, take mantissa bits.
__device__ __forceinline__ int floor_pos(float x) {
    return __float_as_int(__fadd_rz(x, 8388608.0f)) & 0x7FFFFF;
}
// saturate((x+1)/2)
__device__ __forceinline__ float sat01(float x) {
    return __saturatef(fmaf(x, 0.5f, 0.5f));
}

// ---------------------------------------------------------------- K1: histograms
__device__ __forceinline__ void hist_px(int la, int lb,
                                        float fa, float fb, float fc,
                                        float ra, float rb, float rc,
                                        const int* lutA, const int* lutB,
                                        unsigned int* sh)
{
    int da = lutA[la];
    int db = lutB[lb];

    int sbase = (da & 0xFFFF) - 1;
    if (sbase >= 0) {
        int b0 = min(floor_pos(sat01(fa) * 256.0f), 255);
        int b1 = min(floor_pos(sat01(fb) * 256.0f), 255);
        int b2 = min(floor_pos(sat01(fc) * 256.0f), 255);
        atomicAdd(&sh[sbase          + b0], 1u);
        atomicAdd(&sh[sbase +     NB + b1], 1u);
        atomicAdd(&sh[sbase + 2 * NB + b2], 1u);
    }

    int faceval = ((da >> 16) & 1) + ((db >> 16) & 1);
    int tbase = (db & 0xFFFF) - 1;
    if ((faceval | (tbase + 1)) != 0) {
        float scale = (faceval == 2) ? 512.0f : 256.0f;   // faceval==2 implies tbase<0
        int b0 = min(floor_pos(sat01(ra) * scale), 255);
        int b1 = min(floor_pos(sat01(rb) * scale), 255);
        int b2 = min(floor_pos(sat01(rc) * scale), 255);
        if (faceval > 0) {
            atomicAdd(&sh[3 * NB          + b0], 1u);
            atomicAdd(&sh[3 * NB +     NB + b1], 1u);
            atomicAdd(&sh[3 * NB + 2 * NB + b2], 1u);
        }
        if (tbase >= 0) {
            atomicAdd(&sh[tbase          + b0], 1u);
            atomicAdd(&sh[tbase +     NB + b1], 1u);
            atomicAdd(&sh[tbase + 2 * NB + b2], 1u);
        }
    }
}

__global__ void __launch_bounds__(512, 2) hist_kernel(
    const float4* __restrict__ fake, const float4* __restrict__ refb,
    const int4* __restrict__ ma, const int4* __restrict__ mb)
{
    __shared__ unsigned int sh[NHIST * NB];
    __shared__ int lutA[32], lutB[32];
    for (int i = threadIdx.x; i < NHIST * NB; i += 512) sh[i] = 0u;
    if (threadIdx.x < 32) { lutA[threadIdx.x] = c_lutA[threadIdx.x];
                            lutB[threadIdx.x] = c_lutB[threadIdx.x]; }
    __syncthreads();

    int stride = gridDim.x * 512;
    for (int q = blockIdx.x * 512 + threadIdx.x; q < NQ; q += stride) {
        int4   a4 = ma[q],  b4 = mb[q];
        float4 f0 = fake[q], f1 = fake[q + NQ], f2 = fake[q + 2 * NQ];
        float4 r0 = refb[q], r1 = refb[q + NQ], r2 = refb[q + 2 * NQ];
        hist_px(a4.x, b4.x, f0.x, f1.x, f2.x, r0.x, r1.x, r2.x, lutA, lutB, sh);
        hist_px(a4.y, b4.y, f0.y, f1.y, f2.y, r0.y, r1.y, r2.y, lutA, lutB, sh);
        hist_px(a4.z, b4.z, f0.z, f1.z, f2.z, r0.z, r1.z, r2.z, lutA, lutB, sh);
        hist_px(a4.w, b4.w, f0.w, f1.w, f2.w, r0.w, r1.w, r2.w, lutA, lutB, sh);
    }
    __syncthreads();
    for (int i = threadIdx.x; i < NHIST * NB; i += 512) {
        unsigned v = sh[i];
        if (v) atomicAdd(&g_hist[i], v);
    }
}

// ---------------------------------------------------------------- K2: tables + loss
__device__ __forceinline__ float loss_px(int la, float fa, float fb, float fc,
                                         const int* lutA, const float* tbl)
{
    int sbase = ((lutA[la] & 0xFFFF) - 1) >> 1;   // src hist base/2 == region*3*NB
    float s = 0.0f;
    if (sbase >= 0) {
        const float* tb = tbl + sbase;
        float v0 = sat01(fa) * 255.0f;
        float v1 = sat01(fb) * 255.0f;
        float v2 = sat01(fc) * 255.0f;
        int i0 = min(floor_pos(v0), 255);
        int i1 = min(floor_pos(v1), 255);
        int i2 = min(floor_pos(v2), 255);
        s = fabsf(v0 - tb[i0]) + fabsf(v1 - tb[NB + i1]) + fabsf(v2 - tb[2 * NB + i2]);
    }
    return s;
}

__global__ void __launch_bounds__(256) table_loss_kernel(
    const float4* __restrict__ fake, const int4* __restrict__ ma, float* out)
{
    __shared__ float tbl[12 * NB];      // prologue scratch / loss-phase table cache
    __shared__ int lutA[32];
    __shared__ float wsum[8];

    const int tid = threadIdx.x;
    const int bid = blockIdx.x;

    if (tid < 32) lutA[tid] = c_lutA[tid];

    // ---- prologue: blocks 0..11 build one table each (+ self-clean g_hist)
    if (bid < 12) {
        float* rs = tbl;                 // [256] reduce scratch src
        float* rt = tbl + NB;            // [256] reduce scratch tar
        float* cd = tbl + 2 * NB;        // [256] src CDF
        float* ca = tbl + 3 * NB;        // [256] tar CDF
        int region = bid / 3, c = bid % 3;
        int isrc = (region * 6 + c) * NB;
        int itar = (region * 6 + 3 + c) * NB;

        unsigned hs = g_hist[isrc + tid];
        unsigned ht = g_hist[itar + tid];
        g_hist[isrc + tid] = 0u;         // restore zeros for next replay
        g_hist[itar + tid] = 0u;

        // totals: integer counts < 2^24 -> f32 tree reduction is exact
        rs[tid] = (float)hs;
        rt[tid] = (float)ht;
        __syncthreads();
        for (int off = 128; off > 0; off >>= 1) {
            if (tid < off) { rs[tid] += rs[tid + off]; rt[tid] += rt[tid + off]; }
            __syncthreads();
        }
        float tots = fmaxf(rs[0], 1.0f);
        float tott = fmaxf(rt[0], 1.0f);
        __syncthreads();

        // elementwise division (identical rounding to reference), then 8-step scan
        cd[tid] = (float)hs / tots;
        ca[tid] = (float)ht / tott;
        __syncthreads();
        #pragma unroll
        for (int off = 1; off < NB; off <<= 1) {
            float a = (tid >= off) ? cd[tid - off] : 0.0f;
            float b = (tid >= off) ? ca[tid - off] : 0.0f;
            __syncthreads();
            cd[tid] += a;
            ca[tid] += b;
            __syncthreads();
        }

        // table[i] = first j in 1..255 with ca[j-1] <= cd[i] <= ca[j], else i.
        {
            float dc = cd[tid];
            int t = tid;
            for (int k = 0; k < 255; k++) {
                if (dc >= ca[k] && dc <= ca[k + 1]) { t = k + 1; break; }
            }
            if (tid == 0)   t = 0;
            if (tid == 255) t = 255;
            g_tables[bid * NB + tid] = (float)t;
        }
        __syncthreads();
        if (tid == 0) {
            __threadfence();
            atomicAdd(&g_tbar, 1u);
        }
    }

    // ---- wait for all 12 tables (nanosleep backoff: avoid L2 same-address flood)
    if (tid == 0) {
        while (*(volatile unsigned int*)&g_tbar < 12u) { __nanosleep(256); }
        __threadfence();
    }
    __syncthreads();

    // ---- loss phase (proven body)
    for (int i = tid; i < 12 * NB; i += 256) tbl[i] = g_tables[i];
    __syncthreads();

    float acc = 0.0f;
    int stride = gridDim.x * 256;
    for (int q = bid * 256 + tid; q < NQ; q += stride) {
        int4   a4 = ma[q];
        float4 f0 = fake[q], f1 = fake[q + NQ], f2 = fake[q + 2 * NQ];
        acc += loss_px(a4.x, f0.x, f1.x, f2.x, lutA, tbl);
        acc += loss_px(a4.y, f0.y, f1.y, f2.y, lutA, tbl);
        acc += loss_px(a4.z, f0.z, f1.z, f2.z, lutA, tbl);
        acc += loss_px(a4.w, f0.w, f1.w, f2.w, lutA, tbl);
    }

    #pragma unroll
    for (int off = 16; off > 0; off >>= 1)
        acc += __shfl_down_sync(0xffffffffu, acc, off);
    int lane = tid & 31, wid = tid >> 5;
    if (lane == 0) wsum[wid] = acc;
    __syncthreads();
    if (tid == 0) {
        float s = 0.0f;
        #pragma unroll
        for (int i = 0; i < 8; i++) s += wsum[i];
        atomicAdd(&g_acc, (double)s);
        __threadfence();
        unsigned t = atomicAdd(&g_ticket, 1u);
        if (t == (unsigned)(gridDim.x - 1)) {
            double total = *((volatile double*)&g_acc);
            out[0] = (float)(total * (0.1 / 12582912.0));  // 0.1/(3*H*W)
            g_acc = 0.0;
            g_tbar = 0u;
            g_ticket = 0u;
        }
    }
}

// ---------------------------------------------------------------- launch
extern "C" void kernel_launch(void* const* d_in, const int* in_sizes, int n_in,
                              void* d_out, int out_size)
{
    (void)in_sizes; (void)n_in; (void)out_size;
    const float4* fake = (const float4*)d_in[0];
    const float4* refb = (const float4*)d_in[1];
    const int4*   ma   = (const int4*)d_in[2];
    const int4*   mb   = (const int4*)d_in[3];
    float* out = (float*)d_out;

    hist_kernel      <<<296, 512>>>(fake, refb, ma, mb);
    table_loss_kernel<<<LOSS_GRID, 256>>>(fake, ma, out);
}

// round 10
// speedup vs baseline: 1.4493x; 1.0685x over previous
#include <cuda_runtime.h>

// HMLoss: 4-region histogram-matching L1 loss, H=W=2048.
// R10: K2's table dependency removed -- EVERY block computes all 12 matching
// tables redundantly (~2-3us, fully parallel) instead of 580 blocks spinning
// on 12 producer blocks. Warp-per-(table,side) CDF build (shfl-only), binary
// lower-bound search (== linear first-match on monotone CDFs). No g_tables,
// no flag, no wait. g_hist self-clean moved to the ticket-last block.

#define NQ    1048576   // (2048*2048)/4
#define NB    256
#define NHIST 24

__device__ unsigned int g_hist[NHIST * NB];   // zeroed at load; self-cleaning
__device__ double       g_acc;
__device__ unsigned int g_ticket;

#define LOSS_GRID 592

// Packed label LUTs (labels 0..18).
// A (mask_A): low16 = src hist base + 1 (0 = unmasked), bit16 = (label==11)
// B (mask_B): low16 = tar hist base + 1 for hair/eye (0 = none), bit16 = in tar face set
__constant__ int c_lutA[32] = {
    0, 1, 3073, 4609, 3073, 4609, 0,
    1, 1, 0, 1, 1 | (1 << 16), 0, 0,
    1, 0, 0, 1537, 0,
    0,0,0,0,0,0,0,0,0,0,0,0,0
};
__constant__ int c_lutB[32] = {
    0, (1<<16), 3841, 5377, 3841, 5377, 0,
    (1<<16), (1<<16), 0, (1<<16), 0, 0, 0,
    (1<<16), 0, 0, 2305, 0,
    0,0,0,0,0,0,0,0,0,0,0,0,0
};

// floor for x in [0, 2^23): round-toward-zero add of 2^23, take mantissa bits.
__device__ __forceinline__ int floor_pos(float x) {
    return __float_as_int(__fadd_rz(x, 8388608.0f)) & 0x7FFFFF;
}
// saturate((x+1)/2)
__device__ __forceinline__ float sat01(float x) {
    return __saturatef(fmaf(x, 0.5f, 0.5f));
}

// ---------------------------------------------------------------- K1: histograms
__device__ __forceinline__ void hist_px(int la, int lb,
                                        float fa, float fb, float fc,
                                        float ra, float rb, float rc,
                                        const int* lutA, const int* lutB,
                                        unsigned int* sh)
{
    int da = lutA[la];
    int db = lutB[lb];

    int sbase = (da & 0xFFFF) - 1;
    if (sbase >= 0) {
        int b0 = min(floor_pos(sat01(fa) * 256.0f), 255);
        int b1 = min(floor_pos(sat01(fb) * 256.0f), 255);
        int b2 = min(floor_pos(sat01(fc) * 256.0f), 255);
        atomicAdd(&sh[sbase          + b0], 1u);
        atomicAdd(&sh[sbase +     NB + b1], 1u);
        atomicAdd(&sh[sbase + 2 * NB + b2], 1u);
    }

    int faceval = ((da >> 16) & 1) + ((db >> 16) & 1);
    int tbase = (db & 0xFFFF) - 1;
    if ((faceval | (tbase + 1)) != 0) {
        float scale = (faceval == 2) ? 512.0f : 256.0f;   // faceval==2 implies tbase<0
        int b0 = min(floor_pos(sat01(ra) * scale), 255);
        int b1 = min(floor_pos(sat01(rb) * scale), 255);
        int b2 = min(floor_pos(sat01(rc) * scale), 255);
        if (faceval > 0) {
            atomicAdd(&sh[3 * NB          + b0], 1u);
            atomicAdd(&sh[3 * NB +     NB + b1], 1u);
            atomicAdd(&sh[3 * NB + 2 * NB + b2], 1u);
        }
        if (tbase >= 0) {
            atomicAdd(&sh[tbase          + b0], 1u);
            atomicAdd(&sh[tbase +     NB + b1], 1u);
            atomicAdd(&sh[tbase + 2 * NB + b2], 1u);
        }
    }
}

__global__ void __launch_bounds__(512, 2) hist_kernel(
    const float4* __restrict__ fake, const float4* __restrict__ refb,
    const int4* __restrict__ ma, const int4* __restrict__ mb)
{
    __shared__ unsigned int sh[NHIST * NB];
    __shared__ int lutA[32], lutB[32];
    for (int i = threadIdx.x; i < NHIST * NB; i += 512) sh[i] = 0u;
    if (threadIdx.x < 32) { lutA[threadIdx.x] = c_lutA[threadIdx.x];
                            lutB[threadIdx.x] = c_lutB[threadIdx.x]; }
    __syncthreads();

    int stride = gridDim.x * 512;
    for (int q = blockIdx.x * 512 + threadIdx.x; q < NQ; q += stride) {
        int4   a4 = ma[q],  b4 = mb[q];
        float4 f0 = fake[q], f1 = fake[q + NQ], f2 = fake[q + 2 * NQ];
        float4 r0 = refb[q], r1 = refb[q + NQ], r2 = refb[q + 2 * NQ];
        hist_px(a4.x, b4.x, f0.x, f1.x, f2.x, r0.x, r1.x, r2.x, lutA, lutB, sh);
        hist_px(a4.y, b4.y, f0.y, f1.y, f2.y, r0.y, r1.y, r2.y, lutA, lutB, sh);
        hist_px(a4.z, b4.z, f0.z, f1.z, f2.z, r0.z, r1.z, r2.z, lutA, lutB, sh);
        hist_px(a4.w, b4.w, f0.w, f1.w, f2.w, r0.w, r1.w, r2.w, lutA, lutB, sh);
    }
    __syncthreads();
    for (int i = threadIdx.x; i < NHIST * NB; i += 512) {
        unsigned v = sh[i];
        if (v) atomicAdd(&g_hist[i], v);
    }
}

// ---------------------------------------------------------------- K2: tables + loss
__device__ __forceinline__ float loss_px(int la, float fa, float fb, float fc,
                                         const int* lutA, const float* tbl)
{
    int sbase = ((lutA[la] & 0xFFFF) - 1) >> 1;   // src hist base/2 == region*3*NB
    float s = 0.0f;
    if (sbase >= 0) {
        const float* tb = tbl + sbase;
        float v0 = sat01(fa) * 255.0f;
        float v1 = sat01(fb) * 255.0f;
        float v2 = sat01(fc) * 255.0f;
        int i0 = min(floor_pos(v0), 255);
        int i1 = min(floor_pos(v1), 255);
        int i2 = min(floor_pos(v2), 255);
        s = fabsf(v0 - tb[i0]) + fabsf(v1 - tb[NB + i1]) + fabsf(v2 - tb[2 * NB + i2]);
    }
    return s;
}

__global__ void __launch_bounds__(256) table_loss_kernel(
    const float4* __restrict__ fake, const int4* __restrict__ ma, float* out)
{
    // smA: src CDFs then (in-place) tables; smB: tar CDFs
    __shared__ float smA[12 * NB];
    __shared__ float smB[12 * NB];
    __shared__ int lutA[32];
    __shared__ float wsum[8];
    __shared__ int s_last;

    const int tid  = threadIdx.x;
    const int lane = tid & 31;
    const int wid  = tid >> 5;     // 8 warps

    if (tid < 32) lutA[tid] = c_lutA[tid];

    // ---- phase A: build all 24 CDFs, warp-per-(table,side); shfl-only
    #pragma unroll
    for (int round = 0; round < 3; round++) {
        int task = wid + round * 8;             // 0..23
        int rc = task >> 1, side = task & 1;    // rc = region*3 + c
        int region = rc / 3, c = rc - region * 3;
        int hbase = (region * 6 + side * 3 + c) * NB;

        float v[8];
        float tot = 0.0f;
        #pragma unroll
        for (int k = 0; k < 8; k++) {
            v[k] = (float)g_hist[hbase + k * 32 + lane];   // coalesced
            tot += v[k];
        }
        #pragma unroll
        for (int off = 16; off > 0; off >>= 1)
            tot += __shfl_xor_sync(0xffffffffu, tot, off);   // exact: ints < 2^24
        tot = fmaxf(tot, 1.0f);

        float* dst = side ? smB : smA;
        float carry = 0.0f;
        #pragma unroll
        for (int k = 0; k < 8; k++) {
            float x = v[k] / tot;                // elementwise, reference rounding
            #pragma unroll
            for (int off = 1; off < 32; off <<= 1) {
                float y = __shfl_up_sync(0xffffffffu, x, off);
                if (lane >= off) x += y;
            }
            dst[rc * NB + k * 32 + lane] = carry + x;
            carry += __shfl_sync(0xffffffffu, x, 31);
        }
    }
    __syncthreads();

    // ---- phase B: tables via binary lower-bound (== linear first-match)
    #pragma unroll
    for (int r = 0; r < 12; r++) {
        const float* ca = smB + r * NB;
        float dc = smA[r * NB + tid];
        int lo = 1, hi = 255;
        #pragma unroll
        for (int s = 0; s < 8; s++) {
            int mid = (lo + hi) >> 1;
            if (ca[mid] >= dc) hi = mid; else lo = mid + 1;
        }
        bool found = (dc >= ca[lo - 1]) && (dc <= ca[lo]);
        int t = found ? lo : tid;
        if (tid == 0)   t = 0;
        if (tid == 255) t = 255;
        smA[r * NB + tid] = (float)t;            // in-place: only this thread reads dc
    }
    __syncthreads();

    // ---- phase C: loss (proven body), tables live in smA
    float acc = 0.0f;
    int stride = gridDim.x * 256;
    for (int q = blockIdx.x * 256 + tid; q < NQ; q += stride) {
        int4   a4 = ma[q];
        float4 f0 = fake[q], f1 = fake[q + NQ], f2 = fake[q + 2 * NQ];
        acc += loss_px(a4.x, f0.x, f1.x, f2.x, lutA, smA);
        acc += loss_px(a4.y, f0.y, f1.y, f2.y, lutA, smA);
        acc += loss_px(a4.z, f0.z, f1.z, f2.z, lutA, smA);
        acc += loss_px(a4.w, f0.w, f1.w, f2.w, lutA, smA);
    }

    #pragma unroll
    for (int off = 16; off > 0; off >>= 1)
        acc += __shfl_down_sync(0xffffffffu, acc, off);
    if (lane == 0) wsum[wid] = acc;
    __syncthreads();
    if (tid == 0) {
        float s = 0.0f;
        #pragma unroll
        for (int i = 0; i < 8; i++) s += wsum[i];
        atomicAdd(&g_acc, (double)s);
        __threadfence();
        unsigned t = atomicAdd(&g_ticket, 1u);
        s_last = (t == (unsigned)(gridDim.x - 1)) ? 1 : 0;
    }
    __syncthreads();

    // ---- last block: finalize + reset all global state (all reads done: ticket full)
    if (s_last) {
        for (int i = tid; i < NHIST * NB; i += 256) g_hist[i] = 0u;
        if (tid == 0) {
            double total = *((volatile double*)&g_acc);
            out[0] = (float)(total * (0.1 / 12582912.0));  // 0.1/(3*H*W)
            g_acc = 0.0;
            g_ticket = 0u;
        }
    }
}

// ---------------------------------------------------------------- launch
extern "C" void kernel_launch(void* const* d_in, const int* in_sizes, int n_in,
                              void* d_out, int out_size)
{
    (void)in_sizes; (void)n_in; (void)out_size;
    const float4* fake = (const float4*)d_in[0];
    const float4* refb = (const float4*)d_in[1];
    const int4*   ma   = (const int4*)d_in[2];
    const int4*   mb   = (const int4*)d_in[3];
    float* out = (float*)d_out;

    hist_kernel      <<<296, 512>>>(fake, refb, ma, mb);
    table_loss_kernel<<<LOSS_GRID, 256>>>(fake, ma, out);
}